// round 8
// baseline (speedup 1.0000x reference)
#include <cuda_runtime.h>

#define NN   100000
#define EE   1600000
#define EAA  1000000
#define GG   512
#define F_INN 16
#define HH   32

// ---- bucket sort config ----
#define NB        512                 // buckets
#define NPB       196                 // nodes per bucket (512*196 >= NN)
#define EB_INT4   (EE / 4)            // 400000 int4 packets
#define I4_BLK    512                 // int4s per block -> 2048 edges
#define P1_BLOCKS ((EB_INT4 + I4_BLK - 1) / I4_BLK)   // 782

// ---- scratch (device globals) ----
__device__ __align__(16) float g_deg[NN];          // dinv
__device__ __align__(16) float g_y  [NN * HH];     // layer-1 gather source
__device__ __align__(16) float g_y2 [NN * HH];     // layer-2 gather source
__device__ __align__(16) float g_h  [NN * HH];     // layer-2 output
__device__ __align__(16) float g_u  [NN * HH];     // h @ Wbil
__device__ __align__(16) float g_pooled[GG * HH];
__device__ float g_cnt[GG];
__device__ int   g_cnt_i[NN];                      // in-degree (no self loop)
__device__ int   g_pos[NN];                        // CSR row start
__device__ int   g_csr[EE];                        // src ids grouped by dst
__device__ int2  g_part[EE];                       // bucket-partitioned (src,dst)
__device__ int   g_histmat[P1_BLOCKS * NB];        // per-block bucket hist -> offsets
__device__ int   g_bstart[NB];
__device__ int   g_bsize [NB];

// ---------------- build kernels (atomic-free in gmem) ----------------

__global__ void k_p0() {
    int i = blockIdx.x * blockDim.x + threadIdx.x;
    if (i < GG * HH) g_pooled[i] = 0.f;
    if (i < GG)      g_cnt[i] = 0.f;
}

// per-block bucket histogram -> g_histmat[block*NB + b]
__global__ void k_hist(const int* __restrict__ dst) {
    __shared__ int hist[NB];
    for (int i = threadIdx.x; i < NB; i += 256) hist[i] = 0;
    __syncthreads();
    int base = blockIdx.x * I4_BLK + threadIdx.x;
#pragma unroll
    for (int k = 0; k < I4_BLK / 256; k++) {
        int idx = base + k * 256;
        if (idx < EB_INT4) {
            int4 d = reinterpret_cast<const int4*>(dst)[idx];
            atomicAdd(&hist[d.x / NPB], 1);
            atomicAdd(&hist[d.y / NPB], 1);
            atomicAdd(&hist[d.z / NPB], 1);
            atomicAdd(&hist[d.w / NPB], 1);
        }
    }
    __syncthreads();
    for (int i = threadIdx.x; i < NB; i += 256)
        g_histmat[blockIdx.x * NB + i] = hist[i];
}

// single block, NB threads: column totals, bucket scan, rewrite histmat
// in place as per-(block,bucket) exclusive global offsets.
__global__ void k_bscan() {
    __shared__ int s[NB];
    int tid = threadIdx.x;           // 0..NB-1
    int total = 0;
    for (int k = 0; k < P1_BLOCKS; k++) total += g_histmat[k * NB + tid];
    s[tid] = total;
    __syncthreads();
#pragma unroll
    for (int off = 1; off < NB; off <<= 1) {
        int t = (tid >= off) ? s[tid - off] : 0;
        __syncthreads();
        s[tid] += t;
        __syncthreads();
    }
    int start = s[tid] - total;      // exclusive
    g_bstart[tid] = start;
    g_bsize[tid]  = total;
    int run = start;
    for (int k = 0; k < P1_BLOCKS; k++) {
        int h = g_histmat[k * NB + tid];
        g_histmat[k * NB + tid] = run;
        run += h;
    }
}

// scatter edges into bucket-contiguous g_part using smem ranks + precomputed bases
__global__ void k_part(const int* __restrict__ src, const int* __restrict__ dst) {
    __shared__ int bbase[NB];
    __shared__ int lcnt[NB];
    for (int i = threadIdx.x; i < NB; i += 256) {
        bbase[i] = g_histmat[blockIdx.x * NB + i];
        lcnt[i] = 0;
    }
    __syncthreads();
    int base = blockIdx.x * I4_BLK + threadIdx.x;
#pragma unroll
    for (int k = 0; k < I4_BLK / 256; k++) {
        int idx = base + k * 256;
        if (idx < EB_INT4) {
            int4 d  = reinterpret_cast<const int4*>(dst)[idx];
            int4 sv = reinterpret_cast<const int4*>(src)[idx];
            int b0 = d.x / NPB; int r0 = atomicAdd(&lcnt[b0], 1);
            int b1 = d.y / NPB; int r1 = atomicAdd(&lcnt[b1], 1);
            int b2 = d.z / NPB; int r2 = atomicAdd(&lcnt[b2], 1);
            int b3 = d.w / NPB; int r3 = atomicAdd(&lcnt[b3], 1);
            g_part[bbase[b0] + r0] = make_int2(sv.x, d.x);
            g_part[bbase[b1] + r1] = make_int2(sv.y, d.y);
            g_part[bbase[b2] + r2] = make_int2(sv.z, d.z);
            g_part[bbase[b3] + r3] = make_int2(sv.w, d.w);
        }
    }
}

// one block per bucket: local count + scan -> pos/cnt/deg, then ranked CSR fill
__global__ void k_bcsr() {
    __shared__ int cnt[256];
    __shared__ int sc [256];
    __shared__ int lcnt[256];
    int tid = threadIdx.x;
    int b = blockIdx.x;
    cnt[tid] = 0; lcnt[tid] = 0;
    __syncthreads();
    int start = g_bstart[b];
    int size  = g_bsize[b];
    int nodebase = b * NPB;
    for (int i = tid; i < size; i += 256) {
        int2 ed = g_part[start + i];
        atomicAdd(&cnt[ed.y - nodebase], 1);
    }
    __syncthreads();
    int v = cnt[tid];
    sc[tid] = v;
    __syncthreads();
#pragma unroll
    for (int off = 1; off < 256; off <<= 1) {
        int t = (tid >= off) ? sc[tid - off] : 0;
        __syncthreads();
        sc[tid] += t;
        __syncthreads();
    }
    int excl = sc[tid] - v;
    cnt[tid] = excl;                      // reuse as per-node base offset
    int node = nodebase + tid;
    if (tid < NPB && node < NN) {
        g_pos[node]   = start + excl;
        g_cnt_i[node] = v;
        g_deg[node]   = rsqrtf((float)v + 1.0f);
    }
    __syncthreads();
    for (int i = tid; i < size; i += 256) {
        int2 ed = g_part[start + i];
        int ln = ed.y - nodebase;
        int r = atomicAdd(&lcnt[ln], 1);
        g_csr[start + cnt[ln] + r] = ed.x;
    }
}

// ---------------- compute kernels ----------------

// y1 = (x @ W1) * dinv ; 4 threads per node
__global__ void k_mm1(const float* __restrict__ x, const float* __restrict__ W1) {
    __shared__ float sW[F_INN * HH];
    for (int i = threadIdx.x; i < F_INN * HH; i += blockDim.x) sW[i] = W1[i];
    __syncthreads();
    int t = blockIdx.x * blockDim.x + threadIdx.x;
    int node = t >> 2, q = t & 3;
    if (node >= NN) return;
    float acc[8];
#pragma unroll
    for (int j = 0; j < 8; j++) acc[j] = 0.f;
    const float4* xr = reinterpret_cast<const float4*>(x + node * F_INN);
#pragma unroll
    for (int kk = 0; kk < F_INN / 4; kk++) {
        float4 xv = xr[kk];
        float xs[4] = {xv.x, xv.y, xv.z, xv.w};
#pragma unroll
        for (int p = 0; p < 4; p++) {
            int k = kk * 4 + p;
#pragma unroll
            for (int j = 0; j < 8; j++)
                acc[j] = fmaf(xs[p], sW[k * HH + q * 8 + j], acc[j]);
        }
    }
    float dv = g_deg[node];
    int o = node * 8 + q * 2;
    reinterpret_cast<float4*>(g_y)[o]     = make_float4(acc[0]*dv, acc[1]*dv, acc[2]*dv, acc[3]*dv);
    reinterpret_cast<float4*>(g_y)[o + 1] = make_float4(acc[4]*dv, acc[5]*dv, acc[6]*dv, acc[7]*dv);
}

// gather helper: sum y4 rows listed in g_csr[base..base+m) at chunk c
__device__ __forceinline__ float4 gather_rows(const float4* __restrict__ y4,
                                              int base, int m, int c, float4 acc) {
    float4 acc2 = make_float4(0.f, 0.f, 0.f, 0.f);
    int i = 0;
    for (; i + 4 <= m; i += 4) {
        int s0 = g_csr[base + i];
        int s1 = g_csr[base + i + 1];
        int s2 = g_csr[base + i + 2];
        int s3 = g_csr[base + i + 3];
        float4 v0 = y4[s0 * 8 + c];
        float4 v1 = y4[s1 * 8 + c];
        float4 v2 = y4[s2 * 8 + c];
        float4 v3 = y4[s3 * 8 + c];
        acc.x  += v0.x + v1.x; acc.y  += v0.y + v1.y;
        acc.z  += v0.z + v1.z; acc.w  += v0.w + v1.w;
        acc2.x += v2.x + v3.x; acc2.y += v2.y + v3.y;
        acc2.z += v2.z + v3.z; acc2.w += v2.w + v3.w;
    }
    for (; i < m; i++) {
        float4 v = y4[g_csr[base + i] * 8 + c];
        acc.x += v.x; acc.y += v.y; acc.z += v.z; acc.w += v.w;
    }
    acc.x += acc2.x; acc.y += acc2.y; acc.z += acc2.z; acc.w += acc2.w;
    return acc;
}

// fused: CSR gather of y1 + relu epilogue (smem) + @W2 matmul -> y2 (*dinv)
#define NODES_PER_BLK 32
#define HPAD 36
__global__ void k_gmm(const float* __restrict__ b1, const float* __restrict__ W2) {
    __shared__ float sW[HH * HH];
    __shared__ float sb[HH];
    __shared__ float sh[NODES_PER_BLK * HPAD];
    for (int i = threadIdx.x; i < HH * HH; i += blockDim.x) sW[i] = W2[i];
    if (threadIdx.x < HH) sb[threadIdx.x] = b1[threadIdx.x];
    __syncthreads();

    int tid = threadIdx.x;
    int nl = tid >> 3, c = tid & 7;
    int node = blockIdx.x * NODES_PER_BLK + nl;
    bool ok = node < NN;

    if (ok) {
        int base = g_pos[node];
        int m    = g_cnt_i[node];
        const float4* y4 = reinterpret_cast<const float4*>(g_y);
        float4 acc = gather_rows(y4, base, m, c, y4[node * 8 + c]);
        float dv = g_deg[node];
        float* hr = sh + nl * HPAD + c * 4;
        hr[0] = fmaxf(acc.x * dv + sb[c*4+0], 0.f);
        hr[1] = fmaxf(acc.y * dv + sb[c*4+1], 0.f);
        hr[2] = fmaxf(acc.z * dv + sb[c*4+2], 0.f);
        hr[3] = fmaxf(acc.w * dv + sb[c*4+3], 0.f);
    }
    __syncthreads();
    if (!ok) return;

    float a0 = 0.f, a1 = 0.f, a2 = 0.f, a3 = 0.f;
    const float* hrow = sh + nl * HPAD;
#pragma unroll
    for (int k = 0; k < HH; k++) {
        float hv = hrow[k];
        a0 = fmaf(hv, sW[k * HH + c * 4 + 0], a0);
        a1 = fmaf(hv, sW[k * HH + c * 4 + 1], a1);
        a2 = fmaf(hv, sW[k * HH + c * 4 + 2], a2);
        a3 = fmaf(hv, sW[k * HH + c * 4 + 3], a3);
    }
    float dv = g_deg[node];
    reinterpret_cast<float4*>(g_y2)[node * 8 + c] =
        make_float4(a0 * dv, a1 * dv, a2 * dv, a3 * dv);
}

// fused: CSR gather of y2 + epilogue -> g_h, pooling, u = h2 @ Wbil -> g_u
__global__ void k_ghead(const float* __restrict__ b2, const float* __restrict__ Wbil,
                        const int* __restrict__ batch) {
    __shared__ float sW[HH * HH];
    __shared__ float sb[HH];
    __shared__ float sh[NODES_PER_BLK * HPAD];
    for (int i = threadIdx.x; i < HH * HH; i += blockDim.x) sW[i] = Wbil[i];
    if (threadIdx.x < HH) sb[threadIdx.x] = b2[threadIdx.x];
    __syncthreads();

    int tid = threadIdx.x;
    int nl = tid >> 3, c = tid & 7;
    int node = blockIdx.x * NODES_PER_BLK + nl;
    bool ok = node < NN;

    if (ok) {
        int base = g_pos[node];
        int m    = g_cnt_i[node];
        const float4* y4 = reinterpret_cast<const float4*>(g_y2);
        float4 acc = gather_rows(y4, base, m, c, y4[node * 8 + c]);
        float dv = g_deg[node];
        float4 h2;
        h2.x = acc.x * dv + sb[c*4+0];
        h2.y = acc.y * dv + sb[c*4+1];
        h2.z = acc.z * dv + sb[c*4+2];
        h2.w = acc.w * dv + sb[c*4+3];
        float* hr = sh + nl * HPAD + c * 4;
        hr[0] = h2.x; hr[1] = h2.y; hr[2] = h2.z; hr[3] = h2.w;
        reinterpret_cast<float4*>(g_h)[node * 8 + c] = h2;
        int g = batch[node];
        atomicAdd(reinterpret_cast<float4*>(g_pooled) + g * 8 + c, h2);
        if (c == 0) atomicAdd(&g_cnt[g], 1.0f);
    }
    __syncthreads();
    if (!ok) return;

    float a0 = 0.f, a1 = 0.f, a2 = 0.f, a3 = 0.f;
    const float* hrow = sh + nl * HPAD;
#pragma unroll
    for (int k = 0; k < HH; k++) {
        float hv = hrow[k];
        a0 = fmaf(hv, sW[k * HH + c * 4 + 0], a0);
        a1 = fmaf(hv, sW[k * HH + c * 4 + 1], a1);
        a2 = fmaf(hv, sW[k * HH + c * 4 + 2], a2);
        a3 = fmaf(hv, sW[k * HH + c * 4 + 3], a3);
    }
    reinterpret_cast<float4*>(g_u)[node * 8 + c] = make_float4(a0, a1, a2, a3);
}

// edge head (4 threads/edge, 2x float4 per operand) + fused reg head in last block
__global__ void k_edge(const int* __restrict__ asrc, const int* __restrict__ adst,
                       const float* __restrict__ bbil,
                       const float* __restrict__ Wr, const float* __restrict__ br,
                       float* __restrict__ out) {
    if (blockIdx.x == gridDim.x - 1) {
        for (int g = threadIdx.x; g < GG; g += 256) {
            float c = g_cnt[g];
            c = c < 1.f ? 1.f : c;
            float acc = 0.f;
#pragma unroll
            for (int h = 0; h < HH; h++) acc = fmaf(g_pooled[g * HH + h], Wr[h], acc);
            out[g] = acc / c + br[0];
        }
        return;
    }
    long t = (long)blockIdx.x * 256 + threadIdx.x;
    int e = (int)(t >> 2), lane = (int)(t & 3);
    if (e >= EAA) return;
    int s = asrc[e], d = adst[e];
    const float4* u4 = reinterpret_cast<const float4*>(g_u);
    const float4* h4 = reinterpret_cast<const float4*>(g_h);
    float4 a0 = u4[s * 8 + lane];
    float4 b0 = h4[d * 8 + lane];
    float4 a1 = u4[s * 8 + lane + 4];
    float4 b1 = h4[d * 8 + lane + 4];
    float p = a0.x*b0.x + a0.y*b0.y + a0.z*b0.z + a0.w*b0.w
            + a1.x*b1.x + a1.y*b1.y + a1.z*b1.z + a1.w*b1.w;
    p += __shfl_down_sync(0xffffffffu, p, 2, 4);
    p += __shfl_down_sync(0xffffffffu, p, 1, 4);
    if (lane == 0) out[GG + e] = p + bbil[0];
}

// ---------------- launch ----------------

extern "C" void kernel_launch(void* const* d_in, const int* in_sizes, int n_in,
                              void* d_out, int out_size) {
    const float* x    = (const float*)d_in[0];
    const int*   ei   = (const int*)  d_in[1];
    const int*   eia  = (const int*)  d_in[2];
    const int*   batch= (const int*)  d_in[3];
    const float* W1   = (const float*)d_in[4];
    const float* b1   = (const float*)d_in[5];
    const float* W2   = (const float*)d_in[6];
    const float* b2   = (const float*)d_in[7];
    const float* Wr   = (const float*)d_in[8];
    const float* br   = (const float*)d_in[9];
    const float* Wbil = (const float*)d_in[10];
    const float* bbil = (const float*)d_in[11];
    float* out = (float*)d_out;

    const int* src  = ei;
    const int* dst  = ei + EE;
    const int* asrc = eia;
    const int* adst = eia + EAA;

    const int B = 256;

    // atomic-free CSR build (one-wave grids)
    k_p0   <<<(GG * HH + B - 1) / B, B>>>();
    k_hist <<<P1_BLOCKS, B>>>(dst);
    k_bscan<<<1, NB>>>();
    k_part <<<P1_BLOCKS, B>>>(src, dst);
    k_bcsr <<<NB, B>>>();

    // layer 1 matmul, fused gather+relu+layer2 matmul (y1 -> y2)
    k_mm1  <<<(NN * 4 + B - 1) / B, B>>>(x, W1);
    k_gmm  <<<(NN + NODES_PER_BLK - 1) / NODES_PER_BLK, B>>>(b1, W2);

    // fused gather(y2) + epilogue + pooling + bilinear precompute
    k_ghead<<<(NN + NODES_PER_BLK - 1) / NODES_PER_BLK, B>>>(b2, Wbil, batch);

    // edge head + fused reg head
    int edge_blocks = (int)(((long)EAA * 4 + B - 1) / B);
    k_edge <<<edge_blocks + 1, B>>>(asrc, adst, bbil, Wr, br, out);
}

// round 9
// speedup vs baseline: 1.2720x; 1.2720x over previous
#include <cuda_runtime.h>

#define NN   100000
#define EE   1600000
#define EAA  1000000
#define GG   512
#define F_INN 16
#define HH   32

#define SCAN_B 1024
#define SCAN_GRID ((NN + SCAN_B - 1) / SCAN_B)

// ---- scratch (device globals) ----
__device__ __align__(16) float g_deg[NN];          // dinv
__device__ __align__(16) float g_y  [NN * HH];     // layer-1 gather source (y1)
__device__ __align__(16) float g_y2 [NN * HH];     // layer-2 gather source (y2)
__device__ __align__(16) float g_h  [NN * HH];     // layer-2 output (edge head)
__device__ __align__(16) float g_u  [NN * HH];     // h @ Wbil
__device__ __align__(16) float g_pooled[GG * HH];
__device__ float g_cnt[GG];
__device__ int   g_cnt_i[NN];                      // in-degree (no self loop)
__device__ int   g_pos[NN];                        // CSR row start
__device__ int   g_cur[NN];                        // fill cursors
__device__ int   g_csr[EE];                        // src ids grouped by dst
__device__ int   g_total;

// ---------------- build kernels (round-5 proven) ----------------

__global__ void k_zero() {
    int i = blockIdx.x * blockDim.x + threadIdx.x;
    if (i < NN) { g_cnt_i[i] = 0; g_cur[i] = 0; }
    if (i < GG * HH) g_pooled[i] = 0.f;
    if (i < GG)      g_cnt[i] = 0.f;
    if (i == 0)      g_total = 0;
}

__global__ void k_count(const int* __restrict__ dst) {
    int e = blockIdx.x * blockDim.x + threadIdx.x;
    if (e < EE) atomicAdd(&g_cnt_i[dst[e]], 1);
}

// blockwise exclusive scan; block base via one atomicAdd per block.
// also computes dinv = rsqrt(deg+1).
__global__ void k_scan() {
    __shared__ int s[SCAN_B];
    __shared__ int base;
    int tid = threadIdx.x;
    int i = blockIdx.x * SCAN_B + tid;
    int v = (i < NN) ? g_cnt_i[i] : 0;
    s[tid] = v;
    __syncthreads();
#pragma unroll
    for (int off = 1; off < SCAN_B; off <<= 1) {
        int t = (tid >= off) ? s[tid - off] : 0;
        __syncthreads();
        s[tid] += t;
        __syncthreads();
    }
    if (tid == 0) base = atomicAdd(&g_total, s[SCAN_B - 1]);
    __syncthreads();
    if (i < NN) {
        g_pos[i] = base + s[tid] - v;          // exclusive
        g_deg[i] = rsqrtf((float)v + 1.0f);    // dinv incl self-loop
    }
}

__global__ void k_fill(const int* __restrict__ src, const int* __restrict__ dst) {
    int e = blockIdx.x * blockDim.x + threadIdx.x;
    if (e >= EE) return;
    int d = dst[e];
    int slot = atomicAdd(&g_cur[d], 1);
    g_csr[g_pos[d] + slot] = src[e];
}

// ---------------- compute kernels ----------------

// y1 = (x @ W1) * dinv ; 4 threads per node
__global__ void k_mm1(const float* __restrict__ x, const float* __restrict__ W1) {
    __shared__ float sW[F_INN * HH];
    for (int i = threadIdx.x; i < F_INN * HH; i += blockDim.x) sW[i] = W1[i];
    __syncthreads();
    int t = blockIdx.x * blockDim.x + threadIdx.x;
    int node = t >> 2, q = t & 3;
    if (node >= NN) return;
    float acc[8];
#pragma unroll
    for (int j = 0; j < 8; j++) acc[j] = 0.f;
    const float4* xr = reinterpret_cast<const float4*>(x + node * F_INN);
#pragma unroll
    for (int kk = 0; kk < F_INN / 4; kk++) {
        float4 xv = xr[kk];
        float xs[4] = {xv.x, xv.y, xv.z, xv.w};
#pragma unroll
        for (int p = 0; p < 4; p++) {
            int k = kk * 4 + p;
#pragma unroll
            for (int j = 0; j < 8; j++)
                acc[j] = fmaf(xs[p], sW[k * HH + q * 8 + j], acc[j]);
        }
    }
    float dv = g_deg[node];
    int o = node * 8 + q * 2;
    reinterpret_cast<float4*>(g_y)[o]     = make_float4(acc[0]*dv, acc[1]*dv, acc[2]*dv, acc[3]*dv);
    reinterpret_cast<float4*>(g_y)[o + 1] = make_float4(acc[4]*dv, acc[5]*dv, acc[6]*dv, acc[7]*dv);
}

// gather helper: sum y4 rows listed in g_csr[base..base+m) at chunk c, unroll 2
__device__ __forceinline__ float4 gather_rows(const float4* __restrict__ y4,
                                              int base, int m, int c, float4 acc) {
    int i = 0;
    for (; i + 2 <= m; i += 2) {
        int s0 = g_csr[base + i];
        int s1 = g_csr[base + i + 1];
        float4 v0 = y4[s0 * 8 + c];
        float4 v1 = y4[s1 * 8 + c];
        acc.x += v0.x + v1.x; acc.y += v0.y + v1.y;
        acc.z += v0.z + v1.z; acc.w += v0.w + v1.w;
    }
    if (i < m) {
        float4 v = y4[g_csr[base + i] * 8 + c];
        acc.x += v.x; acc.y += v.y; acc.z += v.z; acc.w += v.w;
    }
    return acc;
}

// fused: CSR gather of y1 + relu epilogue (smem) + @W2 matmul -> y2 (*dinv)
#define NODES_PER_BLK 32
#define HPAD 36
__global__ void k_gmm(const float* __restrict__ b1, const float* __restrict__ W2) {
    __shared__ float sW[HH * HH];
    __shared__ float sb[HH];
    __shared__ float sh[NODES_PER_BLK * HPAD];
    for (int i = threadIdx.x; i < HH * HH; i += blockDim.x) sW[i] = W2[i];
    if (threadIdx.x < HH) sb[threadIdx.x] = b1[threadIdx.x];
    __syncthreads();

    int tid = threadIdx.x;
    int nl = tid >> 3, c = tid & 7;
    int node = blockIdx.x * NODES_PER_BLK + nl;
    bool ok = node < NN;

    if (ok) {
        int base = g_pos[node];
        int m    = g_cnt_i[node];
        const float4* y4 = reinterpret_cast<const float4*>(g_y);
        float4 acc = gather_rows(y4, base, m, c, y4[node * 8 + c]);
        float dv = g_deg[node];
        float* hr = sh + nl * HPAD + c * 4;
        hr[0] = fmaxf(acc.x * dv + sb[c*4+0], 0.f);
        hr[1] = fmaxf(acc.y * dv + sb[c*4+1], 0.f);
        hr[2] = fmaxf(acc.z * dv + sb[c*4+2], 0.f);
        hr[3] = fmaxf(acc.w * dv + sb[c*4+3], 0.f);
    }
    __syncthreads();
    if (!ok) return;

    float a0 = 0.f, a1 = 0.f, a2 = 0.f, a3 = 0.f;
    const float* hrow = sh + nl * HPAD;
#pragma unroll
    for (int k = 0; k < HH; k++) {
        float hv = hrow[k];
        a0 = fmaf(hv, sW[k * HH + c * 4 + 0], a0);
        a1 = fmaf(hv, sW[k * HH + c * 4 + 1], a1);
        a2 = fmaf(hv, sW[k * HH + c * 4 + 2], a2);
        a3 = fmaf(hv, sW[k * HH + c * 4 + 3], a3);
    }
    float dv = g_deg[node];
    reinterpret_cast<float4*>(g_y2)[node * 8 + c] =
        make_float4(a0 * dv, a1 * dv, a2 * dv, a3 * dv);
}

// fused: CSR gather of y2 + epilogue -> g_h, pooling, u = h2 @ Wbil -> g_u
__global__ void k_ghead(const float* __restrict__ b2, const float* __restrict__ Wbil,
                        const int* __restrict__ batch) {
    __shared__ float sW[HH * HH];
    __shared__ float sb[HH];
    __shared__ float sh[NODES_PER_BLK * HPAD];
    for (int i = threadIdx.x; i < HH * HH; i += blockDim.x) sW[i] = Wbil[i];
    if (threadIdx.x < HH) sb[threadIdx.x] = b2[threadIdx.x];
    __syncthreads();

    int tid = threadIdx.x;
    int nl = tid >> 3, c = tid & 7;
    int node = blockIdx.x * NODES_PER_BLK + nl;
    bool ok = node < NN;

    if (ok) {
        int base = g_pos[node];
        int m    = g_cnt_i[node];
        const float4* y4 = reinterpret_cast<const float4*>(g_y2);
        float4 acc = gather_rows(y4, base, m, c, y4[node * 8 + c]);
        float dv = g_deg[node];
        float4 h2;
        h2.x = acc.x * dv + sb[c*4+0];
        h2.y = acc.y * dv + sb[c*4+1];
        h2.z = acc.z * dv + sb[c*4+2];
        h2.w = acc.w * dv + sb[c*4+3];
        float* hr = sh + nl * HPAD + c * 4;
        hr[0] = h2.x; hr[1] = h2.y; hr[2] = h2.z; hr[3] = h2.w;
        reinterpret_cast<float4*>(g_h)[node * 8 + c] = h2;
        int g = batch[node];
        atomicAdd(reinterpret_cast<float4*>(g_pooled) + g * 8 + c, h2);
        if (c == 0) atomicAdd(&g_cnt[g], 1.0f);
    }
    __syncthreads();
    if (!ok) return;

    float a0 = 0.f, a1 = 0.f, a2 = 0.f, a3 = 0.f;
    const float* hrow = sh + nl * HPAD;
#pragma unroll
    for (int k = 0; k < HH; k++) {
        float hv = hrow[k];
        a0 = fmaf(hv, sW[k * HH + c * 4 + 0], a0);
        a1 = fmaf(hv, sW[k * HH + c * 4 + 1], a1);
        a2 = fmaf(hv, sW[k * HH + c * 4 + 2], a2);
        a3 = fmaf(hv, sW[k * HH + c * 4 + 3], a3);
    }
    reinterpret_cast<float4*>(g_u)[node * 8 + c] = make_float4(a0, a1, a2, a3);
}

// edge head (4 threads/edge, 2x float4 per operand) + fused reg head in last block
__global__ void k_edge(const int* __restrict__ asrc, const int* __restrict__ adst,
                       const float* __restrict__ bbil,
                       const float* __restrict__ Wr, const float* __restrict__ br,
                       float* __restrict__ out) {
    if (blockIdx.x == gridDim.x - 1) {
        // reg_output[g] = (pooled[g]/max(cnt,1)) @ Wr + br
        for (int g = threadIdx.x; g < GG; g += 256) {
            float c = g_cnt[g];
            c = c < 1.f ? 1.f : c;
            float acc = 0.f;
#pragma unroll
            for (int h = 0; h < HH; h++) acc = fmaf(g_pooled[g * HH + h], Wr[h], acc);
            out[g] = acc / c + br[0];
        }
        return;
    }
    long t = (long)blockIdx.x * 256 + threadIdx.x;
    int e = (int)(t >> 2), lane = (int)(t & 3);
    if (e >= EAA) return;
    int s = asrc[e], d = adst[e];
    const float4* u4 = reinterpret_cast<const float4*>(g_u);
    const float4* h4 = reinterpret_cast<const float4*>(g_h);
    float4 a0 = u4[s * 8 + lane];
    float4 b0 = h4[d * 8 + lane];
    float4 a1 = u4[s * 8 + lane + 4];
    float4 b1 = h4[d * 8 + lane + 4];
    float p = a0.x*b0.x + a0.y*b0.y + a0.z*b0.z + a0.w*b0.w
            + a1.x*b1.x + a1.y*b1.y + a1.z*b1.z + a1.w*b1.w;
    p += __shfl_down_sync(0xffffffffu, p, 2, 4);
    p += __shfl_down_sync(0xffffffffu, p, 1, 4);
    if (lane == 0) out[GG + e] = p + bbil[0];
}

// ---------------- launch ----------------

extern "C" void kernel_launch(void* const* d_in, const int* in_sizes, int n_in,
                              void* d_out, int out_size) {
    const float* x    = (const float*)d_in[0];
    const int*   ei   = (const int*)  d_in[1];
    const int*   eia  = (const int*)  d_in[2];
    const int*   batch= (const int*)  d_in[3];
    const float* W1   = (const float*)d_in[4];
    const float* b1   = (const float*)d_in[5];
    const float* W2   = (const float*)d_in[6];
    const float* b2   = (const float*)d_in[7];
    const float* Wr   = (const float*)d_in[8];
    const float* br   = (const float*)d_in[9];
    const float* Wbil = (const float*)d_in[10];
    const float* bbil = (const float*)d_in[11];
    float* out = (float*)d_out;

    const int* src  = ei;
    const int* dst  = ei + EE;
    const int* asrc = eia;
    const int* adst = eia + EAA;

    const int B = 256;

    // CSR build (round-5 proven)
    k_zero <<<(NN + B - 1) / B, B>>>();
    k_count<<<(EE + B - 1) / B, B>>>(dst);
    k_scan <<<SCAN_GRID, SCAN_B>>>();
    k_fill <<<(EE + B - 1) / B, B>>>(src, dst);

    // layer 1 matmul, then fused gather+relu+layer2 matmul (y1 -> y2)
    k_mm1  <<<(NN * 4 + B - 1) / B, B>>>(x, W1);
    k_gmm  <<<(NN + NODES_PER_BLK - 1) / NODES_PER_BLK, B>>>(b1, W2);

    // fused gather(y2) + epilogue + pooling + bilinear precompute
    k_ghead<<<(NN + NODES_PER_BLK - 1) / NODES_PER_BLK, B>>>(b2, Wbil, batch);

    // edge head + fused reg head
    int edge_blocks = (int)(((long)EAA * 4 + B - 1) / B);
    k_edge <<<edge_blocks + 1, B>>>(asrc, adst, bbil, Wr, br, out);
}

// round 10
// speedup vs baseline: 1.3738x; 1.0800x over previous
#include <cuda_runtime.h>

#define NN   100000
#define EE   1600000
#define EAA  1000000
#define GG   512
#define F_INN 16
#define HH   32
#define SLOTS 96

// ---- scratch (device globals) ----
__device__ __align__(16) float g_deg[NN];          // dinv
__device__ __align__(16) float g_y  [NN * HH];     // layer-1 gather source (y1)
__device__ __align__(16) float g_y2 [NN * HH];     // layer-2 gather source (y2)
__device__ __align__(16) float g_h  [NN * HH];     // layer-2 output (edge head)
__device__ __align__(16) float g_u  [NN * HH];     // h @ Wbil
__device__ __align__(16) float g_pooled[GG * HH];
__device__ float g_cnt[GG];
__device__ int   g_cnt_i[NN];                      // in-degree (no self loop)
__device__ int   g_slot[NN * SLOTS];               // src ids, fixed stride per dst

// ---------------- build kernels ----------------

__global__ void k_zero() {
    int i = blockIdx.x * blockDim.x + threadIdx.x;
    if (i < NN)      g_cnt_i[i] = 0;
    if (i < GG * HH) g_pooled[i] = 0.f;
    if (i < GG)      g_cnt[i] = 0.f;
}

// single pass: count + place src into dst's slot row
__global__ void k_fillslot(const int* __restrict__ src, const int* __restrict__ dst) {
    int e = blockIdx.x * blockDim.x + threadIdx.x;
    if (e >= EE) return;
    int d = dst[e];
    int slot = atomicAdd(&g_cnt_i[d], 1);
    g_slot[d * SLOTS + slot] = src[e];
}

__global__ void k_dinv() {
    int i = blockIdx.x * blockDim.x + threadIdx.x;
    if (i < NN) g_deg[i] = rsqrtf((float)g_cnt_i[i] + 1.0f);
}

// ---------------- compute kernels ----------------

// y1 = (x @ W1) * dinv ; 4 threads per node
__global__ void k_mm1(const float* __restrict__ x, const float* __restrict__ W1) {
    __shared__ float sW[F_INN * HH];
    for (int i = threadIdx.x; i < F_INN * HH; i += blockDim.x) sW[i] = W1[i];
    __syncthreads();
    int t = blockIdx.x * blockDim.x + threadIdx.x;
    int node = t >> 2, q = t & 3;
    if (node >= NN) return;
    float acc[8];
#pragma unroll
    for (int j = 0; j < 8; j++) acc[j] = 0.f;
    const float4* xr = reinterpret_cast<const float4*>(x + node * F_INN);
#pragma unroll
    for (int kk = 0; kk < F_INN / 4; kk++) {
        float4 xv = xr[kk];
        float xs[4] = {xv.x, xv.y, xv.z, xv.w};
#pragma unroll
        for (int p = 0; p < 4; p++) {
            int k = kk * 4 + p;
#pragma unroll
            for (int j = 0; j < 8; j++)
                acc[j] = fmaf(xs[p], sW[k * HH + q * 8 + j], acc[j]);
        }
    }
    float dv = g_deg[node];
    int o = node * 8 + q * 2;
    reinterpret_cast<float4*>(g_y)[o]     = make_float4(acc[0]*dv, acc[1]*dv, acc[2]*dv, acc[3]*dv);
    reinterpret_cast<float4*>(g_y)[o + 1] = make_float4(acc[4]*dv, acc[5]*dv, acc[6]*dv, acc[7]*dv);
}

// gather helper: sum y4 rows listed in g_slot[base..base+m) at chunk c, unroll 2
__device__ __forceinline__ float4 gather_rows(const float4* __restrict__ y4,
                                              int base, int m, int c, float4 acc) {
    int i = 0;
    for (; i + 2 <= m; i += 2) {
        int s0 = g_slot[base + i];
        int s1 = g_slot[base + i + 1];
        float4 v0 = y4[s0 * 8 + c];
        float4 v1 = y4[s1 * 8 + c];
        acc.x += v0.x + v1.x; acc.y += v0.y + v1.y;
        acc.z += v0.z + v1.z; acc.w += v0.w + v1.w;
    }
    if (i < m) {
        float4 v = y4[g_slot[base + i] * 8 + c];
        acc.x += v.x; acc.y += v.y; acc.z += v.z; acc.w += v.w;
    }
    return acc;
}

// fused: slot gather of y1 + relu epilogue (smem) + @W2 matmul -> y2 (*dinv)
#define NODES_PER_BLK 32
#define HPAD 36
__global__ void k_gmm(const float* __restrict__ b1, const float* __restrict__ W2) {
    __shared__ float sW[HH * HH];
    __shared__ float sb[HH];
    __shared__ float sh[NODES_PER_BLK * HPAD];
    for (int i = threadIdx.x; i < HH * HH; i += blockDim.x) sW[i] = W2[i];
    if (threadIdx.x < HH) sb[threadIdx.x] = b1[threadIdx.x];
    __syncthreads();

    int tid = threadIdx.x;
    int nl = tid >> 3, c = tid & 7;
    int node = blockIdx.x * NODES_PER_BLK + nl;
    bool ok = node < NN;

    if (ok) {
        int base = node * SLOTS;
        int m    = g_cnt_i[node];
        const float4* y4 = reinterpret_cast<const float4*>(g_y);
        float4 acc = gather_rows(y4, base, m, c, y4[node * 8 + c]);
        float dv = g_deg[node];
        float* hr = sh + nl * HPAD + c * 4;
        hr[0] = fmaxf(acc.x * dv + sb[c*4+0], 0.f);
        hr[1] = fmaxf(acc.y * dv + sb[c*4+1], 0.f);
        hr[2] = fmaxf(acc.z * dv + sb[c*4+2], 0.f);
        hr[3] = fmaxf(acc.w * dv + sb[c*4+3], 0.f);
    }
    __syncthreads();
    if (!ok) return;

    float a0 = 0.f, a1 = 0.f, a2 = 0.f, a3 = 0.f;
    const float* hrow = sh + nl * HPAD;
#pragma unroll
    for (int k = 0; k < HH; k++) {
        float hv = hrow[k];
        a0 = fmaf(hv, sW[k * HH + c * 4 + 0], a0);
        a1 = fmaf(hv, sW[k * HH + c * 4 + 1], a1);
        a2 = fmaf(hv, sW[k * HH + c * 4 + 2], a2);
        a3 = fmaf(hv, sW[k * HH + c * 4 + 3], a3);
    }
    float dv = g_deg[node];
    reinterpret_cast<float4*>(g_y2)[node * 8 + c] =
        make_float4(a0 * dv, a1 * dv, a2 * dv, a3 * dv);
}

// fused: slot gather of y2 + epilogue -> g_h, pooling, u = h2 @ Wbil -> g_u
__global__ void k_ghead(const float* __restrict__ b2, const float* __restrict__ Wbil,
                        const int* __restrict__ batch) {
    __shared__ float sW[HH * HH];
    __shared__ float sb[HH];
    __shared__ float sh[NODES_PER_BLK * HPAD];
    for (int i = threadIdx.x; i < HH * HH; i += blockDim.x) sW[i] = Wbil[i];
    if (threadIdx.x < HH) sb[threadIdx.x] = b2[threadIdx.x];
    __syncthreads();

    int tid = threadIdx.x;
    int nl = tid >> 3, c = tid & 7;
    int node = blockIdx.x * NODES_PER_BLK + nl;
    bool ok = node < NN;

    if (ok) {
        int base = node * SLOTS;
        int m    = g_cnt_i[node];
        const float4* y4 = reinterpret_cast<const float4*>(g_y2);
        float4 acc = gather_rows(y4, base, m, c, y4[node * 8 + c]);
        float dv = g_deg[node];
        float4 h2;
        h2.x = acc.x * dv + sb[c*4+0];
        h2.y = acc.y * dv + sb[c*4+1];
        h2.z = acc.z * dv + sb[c*4+2];
        h2.w = acc.w * dv + sb[c*4+3];
        float* hr = sh + nl * HPAD + c * 4;
        hr[0] = h2.x; hr[1] = h2.y; hr[2] = h2.z; hr[3] = h2.w;
        reinterpret_cast<float4*>(g_h)[node * 8 + c] = h2;
        int g = batch[node];
        atomicAdd(reinterpret_cast<float4*>(g_pooled) + g * 8 + c, h2);
        if (c == 0) atomicAdd(&g_cnt[g], 1.0f);
    }
    __syncthreads();
    if (!ok) return;

    float a0 = 0.f, a1 = 0.f, a2 = 0.f, a3 = 0.f;
    const float* hrow = sh + nl * HPAD;
#pragma unroll
    for (int k = 0; k < HH; k++) {
        float hv = hrow[k];
        a0 = fmaf(hv, sW[k * HH + c * 4 + 0], a0);
        a1 = fmaf(hv, sW[k * HH + c * 4 + 1], a1);
        a2 = fmaf(hv, sW[k * HH + c * 4 + 2], a2);
        a3 = fmaf(hv, sW[k * HH + c * 4 + 3], a3);
    }
    reinterpret_cast<float4*>(g_u)[node * 8 + c] = make_float4(a0, a1, a2, a3);
}

// edge head (4 threads/edge, 2x float4 per operand) + fused reg head in last block
__global__ void k_edge(const int* __restrict__ asrc, const int* __restrict__ adst,
                       const float* __restrict__ bbil,
                       const float* __restrict__ Wr, const float* __restrict__ br,
                       float* __restrict__ out) {
    if (blockIdx.x == gridDim.x - 1) {
        // reg_output[g] = (pooled[g]/max(cnt,1)) @ Wr + br
        for (int g = threadIdx.x; g < GG; g += 256) {
            float c = g_cnt[g];
            c = c < 1.f ? 1.f : c;
            float acc = 0.f;
#pragma unroll
            for (int h = 0; h < HH; h++) acc = fmaf(g_pooled[g * HH + h], Wr[h], acc);
            out[g] = acc / c + br[0];
        }
        return;
    }
    long t = (long)blockIdx.x * 256 + threadIdx.x;
    int e = (int)(t >> 2), lane = (int)(t & 3);
    if (e >= EAA) return;
    int s = asrc[e], d = adst[e];
    const float4* u4 = reinterpret_cast<const float4*>(g_u);
    const float4* h4 = reinterpret_cast<const float4*>(g_h);
    float4 a0 = u4[s * 8 + lane];
    float4 b0 = h4[d * 8 + lane];
    float4 a1 = u4[s * 8 + lane + 4];
    float4 b1 = h4[d * 8 + lane + 4];
    float p = a0.x*b0.x + a0.y*b0.y + a0.z*b0.z + a0.w*b0.w
            + a1.x*b1.x + a1.y*b1.y + a1.z*b1.z + a1.w*b1.w;
    p += __shfl_down_sync(0xffffffffu, p, 2, 4);
    p += __shfl_down_sync(0xffffffffu, p, 1, 4);
    if (lane == 0) out[GG + e] = p + bbil[0];
}

// ---------------- launch ----------------

extern "C" void kernel_launch(void* const* d_in, const int* in_sizes, int n_in,
                              void* d_out, int out_size) {
    const float* x    = (const float*)d_in[0];
    const int*   ei   = (const int*)  d_in[1];
    const int*   eia  = (const int*)  d_in[2];
    const int*   batch= (const int*)  d_in[3];
    const float* W1   = (const float*)d_in[4];
    const float* b1   = (const float*)d_in[5];
    const float* W2   = (const float*)d_in[6];
    const float* b2   = (const float*)d_in[7];
    const float* Wr   = (const float*)d_in[8];
    const float* br   = (const float*)d_in[9];
    const float* Wbil = (const float*)d_in[10];
    const float* bbil = (const float*)d_in[11];
    float* out = (float*)d_out;

    const int* src  = ei;
    const int* dst  = ei + EE;
    const int* asrc = eia;
    const int* adst = eia + EAA;

    const int B = 256;

    // one-pass slot build
    k_zero    <<<(NN + B - 1) / B, B>>>();
    k_fillslot<<<(EE + B - 1) / B, B>>>(src, dst);
    k_dinv    <<<(NN + B - 1) / B, B>>>();

    // layer 1 matmul, then fused gather+relu+layer2 matmul (y1 -> y2)
    k_mm1  <<<(NN * 4 + B - 1) / B, B>>>(x, W1);
    k_gmm  <<<(NN + NODES_PER_BLK - 1) / NODES_PER_BLK, B>>>(b1, W2);

    // fused gather(y2) + epilogue + pooling + bilinear precompute
    k_ghead<<<(NN + NODES_PER_BLK - 1) / NODES_PER_BLK, B>>>(b2, Wbil, batch);

    // edge head + fused reg head
    int edge_blocks = (int)(((long)EAA * 4 + B - 1) / B);
    k_edge <<<edge_blocks + 1, B>>>(asrc, adst, bbil, Wr, br, out);
}